// round 13
// baseline (speedup 1.0000x reference)
#include <cuda_runtime.h>
#include <cuda_bf16.h>
#include <cstdint>

// Problem constants
#define T_  4
#define B_  4
#define N_  1024
#define D_  512
#define H_  8
#define HD_ 64
#define M_  (T_*B_*N_)     // 16384 rows
#define ROWU 512           // packed row width in u32: [hi 256][mid 256]

// Scratch (no cudaMalloc). Packed bf16 (hi,mid) plane buffers, u32 units.
__device__ uint32_t gU_x2  [(size_t)M_*ROWU];   // x packed; reused as ctx packed
__device__ uint32_t gU_q2  [(size_t)M_*ROWU];
__device__ uint32_t gU_k2  [(size_t)M_*ROWU];
__device__ uint32_t gU_v2  [(size_t)M_*ROWU];
__device__ uint32_t gU_v2t [(size_t)M_*ROWU];   // V transposed per head
__device__ uint32_t gU_wqkv2[(size_t)3*D_*ROWU]; // wq|wk|wv packed, rows 0..1535
__device__ uint32_t gU_wo2 [(size_t)D_*ROWU];
__device__ float    g_bias3[3*D_];               // bq|bk|bv

// ---------------------------------------------------------------------------
// bf16 split + mma + ldmatrix helpers
// ---------------------------------------------------------------------------
__device__ __forceinline__ uint32_t bpack(__nv_bfloat16 a, __nv_bfloat16 b) {
    return (uint32_t)__bfloat16_as_ushort(a) |
           ((uint32_t)__bfloat16_as_ushort(b) << 16);
}
__device__ __forceinline__ void split2(float x0, float x1,
                                       uint32_t& hi, uint32_t& mid) {
    __nv_bfloat16 h0 = __float2bfloat16(x0);
    __nv_bfloat16 h1 = __float2bfloat16(x1);
    __nv_bfloat16 m0 = __float2bfloat16(x0 - __bfloat162float(h0));
    __nv_bfloat16 m1 = __float2bfloat16(x1 - __bfloat162float(h1));
    hi = bpack(h0, h1); mid = bpack(m0, m1);
}
__device__ __forceinline__ void mma_bf16(float c[4], const uint32_t a[4],
                                         uint32_t b0, uint32_t b1) {
    asm volatile(
        "mma.sync.aligned.m16n8k16.row.col.f32.bf16.bf16.f32 "
        "{%0,%1,%2,%3}, {%4,%5,%6,%7}, {%8,%9}, {%0,%1,%2,%3};"
        : "+f"(c[0]), "+f"(c[1]), "+f"(c[2]), "+f"(c[3])
        : "r"(a[0]), "r"(a[1]), "r"(a[2]), "r"(a[3]), "r"(b0), "r"(b1));
}
__device__ __forceinline__ void mma3b(float c[4],
                                      const uint32_t ah[4], const uint32_t am[4],
                                      uint32_t bh0, uint32_t bh1,
                                      uint32_t bm0, uint32_t bm1) {
    mma_bf16(c, ah, bh0, bh1);
    mma_bf16(c, ah, bm0, bm1);
    mma_bf16(c, am, bh0, bh1);
}
__device__ __forceinline__ void ldm_x4(uint32_t& r0, uint32_t& r1,
                                       uint32_t& r2, uint32_t& r3, uint32_t addr) {
    asm volatile("ldmatrix.sync.aligned.m8n8.x4.shared.b16 {%0,%1,%2,%3}, [%4];"
                 : "=r"(r0), "=r"(r1), "=r"(r2), "=r"(r3) : "r"(addr));
}
__device__ __forceinline__ void cpa16(uint32_t saddr, const void* gptr) {
    asm volatile("cp.async.cg.shared.global [%0], [%1], 16;\n"
                 :: "r"(saddr), "l"(gptr));
}
__device__ __forceinline__ uint32_t s2u(const void* p) {
    return (uint32_t)__cvta_generic_to_shared(p);
}

// ---------------------------------------------------------------------------
// Fused pack: one launch packs x + wq/wk/wv (-> wqkv2) + wo (-> wo2)
// ---------------------------------------------------------------------------
#define XQ_ (M_*128)
#define WQ_ (D_*128)
#define PACK_TOTAL (XQ_ + 4*WQ_)

__global__ void pack_all_kernel(
    const float* __restrict__ x,
    const float* __restrict__ wq, const float* __restrict__ wk,
    const float* __restrict__ wv, const float* __restrict__ wo,
    const float* __restrict__ bq, const float* __restrict__ bk,
    const float* __restrict__ bv,
    uint32_t* __restrict__ x2, uint32_t* __restrict__ wqkv2,
    uint32_t* __restrict__ wo2, float* __restrict__ bias3)
{
    int q = blockIdx.x * blockDim.x + threadIdx.x;
    if (q < 3 * D_)
        bias3[q] = (q < D_) ? bq[q] : (q < 2*D_) ? bk[q - D_] : bv[q - 2*D_];
    if (q >= PACK_TOTAL) return;

    const float* src; uint32_t* dst; int j;
    if (q < XQ_) { src = x; dst = x2; j = q; }
    else {
        int w = (q - XQ_) >> 16;           // WQ_ = 65536
        j = (q - XQ_) & 65535;
        src = (w == 0) ? wq : (w == 1) ? wk : (w == 2) ? wv : wo;
        dst = (w < 3) ? wqkv2 + (size_t)w * D_ * ROWU : wo2;
    }
    float4 s = ((const float4*)src)[j];
    int p = 2 * j, r = p >> 8, c = p & 255;
    uint32_t h0, m0, h1, m1;
    split2(s.x, s.y, h0, m0);
    split2(s.z, s.w, h1, m1);
    *(uint2*)&dst[(size_t)r * ROWU + c]       = make_uint2(h0, h1);
    *(uint2*)&dst[(size_t)r * ROWU + 256 + c] = make_uint2(m0, m1);
}

// ---------------------------------------------------------------------------
// V transpose: v2 [tok][ch planes] -> v2t [head][ch][hi 512 | mid 512]
// ---------------------------------------------------------------------------
__global__ void transpose_v_kernel(const uint32_t* __restrict__ v2,
                                   uint32_t* __restrict__ v2t)
{
    __shared__ uint32_t ts[32][65];

    const int head = blockIdx.x;
    const int h    = head & (H_ - 1);
    const int tb   = head >> 3;
    const int k0   = blockIdx.y * 32;
    const int tokb = tb * N_ + k0;

    for (int i = threadIdx.x; i < 32 * 64; i += 128) {
        int tok = i >> 6, c = i & 63;
        size_t src = (size_t)(tokb + tok) * ROWU + h * 32 +
                     (c < 32 ? c : 256 + (c - 32));
        ts[tok][c] = v2[src];
    }
    __syncthreads();

    const size_t outb = (size_t)head * (64 * 1024);
    for (int i = threadIdx.x; i < 64 * 32; i += 128) {
        int ch = i >> 5, rest = i & 31;
        int plane = rest >> 4, j = rest & 15;
        uint32_t w0 = ts[2 * j    ][plane * 32 + (ch >> 1)];
        uint32_t w1 = ts[2 * j + 1][plane * 32 + (ch >> 1)];
        uint16_t e0 = (ch & 1) ? (uint16_t)(w0 >> 16) : (uint16_t)(w0 & 0xffff);
        uint16_t e1 = (ch & 1) ? (uint16_t)(w1 >> 16) : (uint16_t)(w1 & 0xffff);
        v2t[outb + (size_t)ch * 1024 + plane * 512 + (k0 >> 1) + j] =
            (uint32_t)e0 | ((uint32_t)e1 << 16);
    }
}

// ---------------------------------------------------------------------------
// GEMM common: block 128x128, 256 thr (4Mx2N warps), 3-stage cp.async with
// the PROVEN round-10 shape: wait -> sync -> compute -> sync -> refill.
// ldmatrix operand fetch. Smem chunk row: [hi 16 u32][mid 16][pad 4] = 36.
// ---------------------------------------------------------------------------
#define GSTR  36
#define GSTG  (128*GSTR)
#define NCHUNK 16
#define GNST  3

#define GEMM_PROLOG(A2PTR, W2PTR)                                              \
    extern __shared__ uint32_t smg[];                                          \
    uint32_t* Abuf[GNST] = { smg, smg + GSTG, smg + 2*GSTG };                  \
    uint32_t* Wbuf[GNST] = { smg + 3*GSTG, smg + 4*GSTG, smg + 5*GSTG };       \
    const int tid  = threadIdx.x;                                              \
    const int lane = tid & 31, warp = tid >> 5;                                \
    const int g    = lane >> 2, tg = lane & 3;                                 \
    const int wm   = (warp >> 1) * 32;                                         \
    const int wn   = (warp & 1) * 64;                                          \
    const int mb   = blockIdx.y * 128, nb = blockIdx.x * 128;                  \
    const uint32_t aOff = (uint32_t)((wm + (lane & 15)) * GSTR + (lane >> 4) * 4); \
    const uint32_t wOff = (uint32_t)((wn + (lane & 7)) * GSTR +                \
                                     ((lane >> 3) & 1) * 4 +                   \
                                     (lane >> 4) * 8 * GSTR);                  \
    auto load_stage = [&](int t, int buf) {                                    \
        _Pragma("unroll")                                                      \
        for (int l = tid; l < 1024; l += 256) {                                \
            int r = l >> 3, part = l & 7;                                      \
            size_t src; uint32_t dst;                                          \
            if (part < 4) {                                                    \
                src = (size_t)(mb + r) * ROWU + 16 * t + 4 * part;             \
                dst = s2u(&Abuf[buf][r * GSTR + 4 * part]);                    \
            } else {                                                           \
                src = (size_t)(mb + r) * ROWU + 256 + 16 * t + 4 * (part - 4); \
                dst = s2u(&Abuf[buf][r * GSTR + 16 + 4 * (part - 4)]);         \
            }                                                                  \
            cpa16(dst, &(A2PTR)[src]);                                         \
        }                                                                      \
        _Pragma("unroll")                                                      \
        for (int l = tid; l < 1024; l += 256) {                                \
            int r = l >> 3, part = l & 7;                                      \
            size_t src; uint32_t dst;                                          \
            if (part < 4) {                                                    \
                src = (size_t)(nb + r) * ROWU + 16 * t + 4 * part;             \
                dst = s2u(&Wbuf[buf][r * GSTR + 4 * part]);                    \
            } else {                                                           \
                src = (size_t)(nb + r) * ROWU + 256 + 16 * t + 4 * (part - 4); \
                dst = s2u(&Wbuf[buf][r * GSTR + 16 + 4 * (part - 4)]);         \
            }                                                                  \
            cpa16(dst, &(W2PTR)[src]);                                         \
        }                                                                      \
    };                                                                         \
    float acc[2][8][4];                                                        \
    _Pragma("unroll")                                                          \
    for (int i = 0; i < 2; i++)                                                \
        _Pragma("unroll")                                                      \
        for (int j = 0; j < 8; j++)                                            \
            _Pragma("unroll")                                                  \
            for (int l = 0; l < 4; l++) acc[i][j][l] = 0.f;                    \
    _Pragma("unroll")                                                          \
    for (int p = 0; p < GNST; p++) {                                           \
        load_stage(p, p);                                                      \
        asm volatile("cp.async.commit_group;\n" ::: "memory");                 \
    }                                                                          \
    for (int t = 0; t < NCHUNK; t++) {                                         \
        asm volatile("cp.async.wait_group 2;\n" ::: "memory");                 \
        __syncthreads();                                                       \
        const int buf = t % GNST;                                              \
        const uint32_t aBase = s2u(Abuf[buf]) + 4 * aOff;                      \
        const uint32_t wBase = s2u(Wbuf[buf]) + 4 * wOff;                      \
        _Pragma("unroll")                                                      \
        for (int s = 0; s < 2; s++) {                                          \
            uint32_t ah[2][4], am[2][4];                                       \
            _Pragma("unroll")                                                  \
            for (int mi = 0; mi < 2; mi++) {                                   \
                ldm_x4(ah[mi][0], ah[mi][1], ah[mi][2], ah[mi][3],             \
                       aBase + 4 * (16 * mi * GSTR + 8 * s));                  \
                ldm_x4(am[mi][0], am[mi][1], am[mi][2], am[mi][3],             \
                       aBase + 4 * (16 * mi * GSTR + 16 + 8 * s));             \
            }                                                                  \
            _Pragma("unroll")                                                  \
            for (int njp = 0; njp < 4; njp++) {                                \
                uint32_t bh0, bh1, bh2, bh3, bm0, bm1, bm2, bm3;               \
                ldm_x4(bh0, bh1, bh2, bh3,                                     \
                       wBase + 4 * (16 * njp * GSTR + 8 * s));                 \
                ldm_x4(bm0, bm1, bm2, bm3,                                     \
                       wBase + 4 * (16 * njp * GSTR + 16 + 8 * s));            \
                mma3b(acc[0][2*njp    ], ah[0], am[0], bh0, bh1, bm0, bm1);    \
                mma3b(acc[1][2*njp    ], ah[1], am[1], bh0, bh1, bm0, bm1);    \
                mma3b(acc[0][2*njp + 1], ah[0], am[0], bh2, bh3, bm2, bm3);    \
                mma3b(acc[1][2*njp + 1], ah[1], am[1], bh2, bh3, bm2, bm3);    \
            }                                                                  \
        }                                                                      \
        __syncthreads();                                                       \
        if (t + GNST < NCHUNK) load_stage(t + GNST, buf);                      \
        asm volatile("cp.async.commit_group;\n" ::: "memory");                 \
    }

// ---------------------------------------------------------------------------
// Fused QKV GEMM: W = wqkv2 (1536 rows), bias3 concat, split-packed output
// routed to q2/k2/v2 by column segment. Grid (12, 128).
// ---------------------------------------------------------------------------
__global__ __launch_bounds__(256, 2) void gemm_qkv_kernel(
    const uint32_t* __restrict__ A2, const uint32_t* __restrict__ W2,
    const float* __restrict__ bias3,
    uint32_t* __restrict__ q2, uint32_t* __restrict__ k2,
    uint32_t* __restrict__ v2)
{
    GEMM_PROLOG(A2, W2)

    const int seg = nb >> 9;                       // 0=q,1=k,2=v (const/block)
    uint32_t* C = (seg == 0) ? q2 : (seg == 1) ? k2 : v2;

    #pragma unroll
    for (int mi = 0; mi < 2; mi++) {
        int r0 = mb + wm + mi * 16 + g;
        #pragma unroll
        for (int nj = 0; nj < 8; nj++) {
            int c0g = nb + wn + nj * 8 + 2 * tg;   // global col in [0,1536)
            int c0  = c0g & 511;                   // col within segment
            float bia0 = bias3[c0g], bia1 = bias3[c0g + 1];
            float v00 = acc[mi][nj][0] + bia0;
            float v01 = acc[mi][nj][1] + bia1;
            float v10 = acc[mi][nj][2] + bia0;
            float v11 = acc[mi][nj][3] + bia1;
            uint32_t hi, mid;
            split2(v00, v01, hi, mid);
            C[(size_t)r0 * ROWU + (c0 >> 1)]       = hi;
            C[(size_t)r0 * ROWU + 256 + (c0 >> 1)] = mid;
            split2(v10, v11, hi, mid);
            C[(size_t)(r0 + 8) * ROWU + (c0 >> 1)]       = hi;
            C[(size_t)(r0 + 8) * ROWU + 256 + (c0 >> 1)] = mid;
        }
    }
}

// ---------------------------------------------------------------------------
// O projection GEMM: plain float output. Grid (4, 128).
// ---------------------------------------------------------------------------
__global__ __launch_bounds__(256, 2) void gemm_o_kernel(
    const uint32_t* __restrict__ A2, const uint32_t* __restrict__ W2,
    const float* __restrict__ bias, float* __restrict__ C)
{
    GEMM_PROLOG(A2, W2)

    #pragma unroll
    for (int mi = 0; mi < 2; mi++) {
        int r0 = mb + wm + mi * 16 + g;
        #pragma unroll
        for (int nj = 0; nj < 8; nj++) {
            int c0 = nb + wn + nj * 8 + 2 * tg;
            float bia0 = bias[c0], bia1 = bias[c0 + 1];
            *(float2*)&C[(size_t)r0 * D_ + c0] =
                make_float2(acc[mi][nj][0] + bia0, acc[mi][nj][1] + bia1);
            *(float2*)&C[(size_t)(r0 + 8) * D_ + c0] =
                make_float2(acc[mi][nj][2] + bia0, acc[mi][nj][3] + bia1);
        }
    }
}

// ---------------------------------------------------------------------------
// bf16-split attention — EXACT round-10 structure (two syncs per tile,
// refill after compute, wait_group 2, 3 stages). 128 thr / 4 warps.
// ---------------------------------------------------------------------------
#define KSTR 68
#define VSTR 36
#define KTILE (32*KSTR)
#define VTILE (64*VSTR)
#define NSTAGE 3
#define NTILES (N_/32)

__global__ __launch_bounds__(128, 4) void attn_bf16_kernel(
    const uint32_t* __restrict__ q2, const uint32_t* __restrict__ k2,
    const uint32_t* __restrict__ v2t, uint32_t* __restrict__ ctx2)
{
    extern __shared__ uint32_t sma[];
    uint32_t* Kb[NSTAGE];
    uint32_t* Vb[NSTAGE];
    #pragma unroll
    for (int i = 0; i < NSTAGE; i++) {
        Kb[i] = sma + i * KTILE;
        Vb[i] = sma + NSTAGE * KTILE + i * VTILE;
    }

    const int tid  = threadIdx.x;
    const int lane = tid & 31, warp = tid >> 5;
    const int g    = lane >> 2, tg = lane & 3;
    const int wm   = warp * 16;

    const int hidx = blockIdx.y;
    const int h    = hidx & (H_ - 1);
    const int tb   = hidx >> 3;
    const int tokb = tb * N_;
    const size_t headv = (size_t)hidx * (64 * 1024);
    const int q0   = blockIdx.x * 64;

    const uint32_t kOff = (uint32_t)((lane & 7) * KSTR +
                                     ((lane >> 3) & 1) * 4 +
                                     (lane >> 4) * 8 * KSTR);
    const uint32_t vOff = (uint32_t)((lane & 7) * VSTR +
                                     ((lane >> 3) & 1) * 4 +
                                     (lane >> 4) * 8 * VSTR);

    auto load_tile = [&](int t, int buf) {
        const int k0 = 32 * t;
        #pragma unroll
        for (int l = tid; l < 512; l += 128) {   // K: 32 keys x 64 u32
            int key = l >> 4, part = l & 15;
            size_t rowb = (size_t)(tokb + k0 + key) * ROWU + h * 32;
            size_t src; uint32_t dst;
            if (part < 8) {
                src = rowb + 4 * part;
                dst = s2u(&Kb[buf][key * KSTR + 4 * part]);
            } else {
                src = rowb + 256 + 4 * (part - 8);
                dst = s2u(&Kb[buf][key * KSTR + 32 + 4 * (part - 8)]);
            }
            cpa16(dst, &k2[src]);
        }
        #pragma unroll
        for (int l = tid; l < 512; l += 128) {   // Vt: 64 ch x 32 u32
            int ch = l >> 3, part = l & 7;
            size_t vrow = headv + (size_t)ch * 1024;
            size_t src; uint32_t dst;
            if (part < 4) {
                src = vrow + (k0 >> 1) + 4 * part;
                dst = s2u(&Vb[buf][ch * VSTR + 4 * part]);
            } else {
                src = vrow + 512 + (k0 >> 1) + 4 * (part - 4);
                dst = s2u(&Vb[buf][ch * VSTR + 16 + 4 * (part - 4)]);
            }
            cpa16(dst, &v2t[src]);
        }
    };

    #pragma unroll
    for (int p = 0; p < NSTAGE; p++) {
        load_tile(p, p);
        asm volatile("cp.async.commit_group;\n" ::: "memory");
    }

    // ---- Q fragments -> registers ----
    uint32_t qh[4][4], qm[4][4];
    {
        size_t rA = (size_t)(tokb + q0 + wm + g) * ROWU + h * 32;
        size_t rB = rA + (size_t)8 * ROWU;
        #pragma unroll
        for (int s = 0; s < 4; s++) {
            qh[s][0] = q2[rA + 8*s + tg];        qh[s][1] = q2[rB + 8*s + tg];
            qh[s][2] = q2[rA + 8*s + tg + 4];    qh[s][3] = q2[rB + 8*s + tg + 4];
            qm[s][0] = q2[rA + 256 + 8*s + tg];      qm[s][1] = q2[rB + 256 + 8*s + tg];
            qm[s][2] = q2[rA + 256 + 8*s + tg + 4];  qm[s][3] = q2[rB + 256 + 8*s + tg + 4];
        }
    }

    float accPV[8][4];
    #pragma unroll
    for (int j = 0; j < 8; j++)
        #pragma unroll
        for (int l = 0; l < 4; l++) accPV[j][l] = 0.f;
    float dA = 0.f, dB = 0.f;

    int buf = 0;
    for (int t = 0; t < NTILES; t++) {
        asm volatile("cp.async.wait_group 2;\n" ::: "memory");
        __syncthreads();

        const uint32_t kBase = s2u(Kb[buf]) + 4 * kOff;
        const uint32_t vBase = s2u(Vb[buf]) + 4 * vOff;

        // ---- S = Q K^T : 16 rows x 32 keys ----
        float accS[4][4];
        #pragma unroll
        for (int j = 0; j < 4; j++)
            #pragma unroll
            for (int l = 0; l < 4; l++) accS[j][l] = 0.f;

        #pragma unroll
        for (int s = 0; s < 4; s++) {
            #pragma unroll
            for (int njp = 0; njp < 2; njp++) {
                uint32_t bh0, bh1, bh2, bh3, bm0, bm1, bm2, bm3;
                ldm_x4(bh0, bh1, bh2, bh3,
                       kBase + 4 * (16 * njp * KSTR + 8 * s));
                ldm_x4(bm0, bm1, bm2, bm3,
                       kBase + 4 * (16 * njp * KSTR + 32 + 8 * s));
                mma3b(accS[2*njp    ], qh[s], qm[s], bh0, bh1, bm0, bm1);
                mma3b(accS[2*njp + 1], qh[s], qm[s], bh2, bh3, bm2, bm3);
            }
        }

        // ---- P = relu(S/8) in-lane -> A frags; denom; PV ----
        #pragma unroll
        for (int kb = 0; kb < 2; kb++) {
            float p0 = fmaxf(accS[2*kb    ][0] * 0.125f, 0.f);
            float p1 = fmaxf(accS[2*kb    ][1] * 0.125f, 0.f);
            float p2 = fmaxf(accS[2*kb    ][2] * 0.125f, 0.f);
            float p3 = fmaxf(accS[2*kb    ][3] * 0.125f, 0.f);
            float p4 = fmaxf(accS[2*kb + 1][0] * 0.125f, 0.f);
            float p5 = fmaxf(accS[2*kb + 1][1] * 0.125f, 0.f);
            float p6 = fmaxf(accS[2*kb + 1][2] * 0.125f, 0.f);
            float p7 = fmaxf(accS[2*kb + 1][3] * 0.125f, 0.f);
            dA += p0 + p1 + p4 + p5;
            dB += p2 + p3 + p6 + p7;

            uint32_t ah[4], am[4];
            split2(p0, p1, ah[0], am[0]);
            split2(p2, p3, ah[1], am[1]);
            split2(p4, p5, ah[2], am[2]);
            split2(p6, p7, ah[3], am[3]);

            #pragma unroll
            for (int njp = 0; njp < 4; njp++) {
                uint32_t bh0, bh1, bh2, bh3, bm0, bm1, bm2, bm3;
                ldm_x4(bh0, bh1, bh2, bh3,
                       vBase + 4 * (16 * njp * VSTR + 8 * kb));
                ldm_x4(bm0, bm1, bm2, bm3,
                       vBase + 4 * (16 * njp * VSTR + 16 + 8 * kb));
                mma3b(accPV[2*njp    ], ah, am, bh0, bh1, bm0, bm1);
                mma3b(accPV[2*njp + 1], ah, am, bh2, bh3, bm2, bm3);
            }
        }
        __syncthreads();   // all warps done with buf before refill

        if (t + NSTAGE < NTILES) load_tile(t + NSTAGE, buf);
        asm volatile("cp.async.commit_group;\n" ::: "memory");

        buf = (buf == NSTAGE - 1) ? 0 : buf + 1;
    }

    // ---- denominator reduce over tg lanes ----
    dA += __shfl_xor_sync(0xffffffffu, dA, 1);
    dA += __shfl_xor_sync(0xffffffffu, dA, 2);
    dB += __shfl_xor_sync(0xffffffffu, dB, 1);
    dB += __shfl_xor_sync(0xffffffffu, dB, 2);
    const float invA = 1.f / (dA + 1e-6f);
    const float invB = 1.f / (dB + 1e-6f);

    // ---- write ctx packed (planes) for O projection ----
    size_t rA = (size_t)(tokb + q0 + wm + g) * ROWU + h * 32;
    size_t rB = rA + (size_t)8 * ROWU;
    #pragma unroll
    for (int nj = 0; nj < 8; nj++) {
        uint32_t hi, mid;
        split2(accPV[nj][0] * invA, accPV[nj][1] * invA, hi, mid);
        ctx2[rA + 4*nj + tg]       = hi;
        ctx2[rA + 256 + 4*nj + tg] = mid;
        split2(accPV[nj][2] * invB, accPV[nj][3] * invB, hi, mid);
        ctx2[rB + 4*nj + tg]       = hi;
        ctx2[rB + 256 + 4*nj + tg] = mid;
    }
}

// ---------------------------------------------------------------------------
// Launcher. Input order: x, wq, bq, wk, bk, wv, bv, wo, bo
// ---------------------------------------------------------------------------
extern "C" void kernel_launch(void* const* d_in, const int* in_sizes, int n_in,
                              void* d_out, int out_size)
{
    const float* x  = (const float*)d_in[0];
    const float* wq = (const float*)d_in[1];
    const float* bq = (const float*)d_in[2];
    const float* wk = (const float*)d_in[3];
    const float* bk = (const float*)d_in[4];
    const float* wv = (const float*)d_in[5];
    const float* bv = (const float*)d_in[6];
    const float* wo = (const float*)d_in[7];
    const float* bo = (const float*)d_in[8];
    float* out = (float*)d_out;

    uint32_t *x2, *q2, *k2, *v2, *v2t, *wqkv2, *wo2;
    float* bias3;
    cudaGetSymbolAddress((void**)&x2,    gU_x2);
    cudaGetSymbolAddress((void**)&q2,    gU_q2);
    cudaGetSymbolAddress((void**)&k2,    gU_k2);
    cudaGetSymbolAddress((void**)&v2,    gU_v2);
    cudaGetSymbolAddress((void**)&v2t,   gU_v2t);
    cudaGetSymbolAddress((void**)&wqkv2, gU_wqkv2);
    cudaGetSymbolAddress((void**)&wo2,   gU_wo2);
    cudaGetSymbolAddress((void**)&bias3, g_bias3);

    const int gemm_smem = 2 * GNST * GSTG * (int)sizeof(uint32_t);          // 110,592 B
    const int attn_smem = NSTAGE * (KTILE + VTILE) * (int)sizeof(uint32_t); // 53,760 B
    cudaFuncSetAttribute(gemm_qkv_kernel,
        cudaFuncAttributeMaxDynamicSharedMemorySize, gemm_smem);
    cudaFuncSetAttribute(gemm_o_kernel,
        cudaFuncAttributeMaxDynamicSharedMemorySize, gemm_smem);
    cudaFuncSetAttribute(attn_bf16_kernel,
        cudaFuncAttributeMaxDynamicSharedMemorySize, attn_smem);

    // ---- fused pack (x + 4 weights + bias concat) ----
    pack_all_kernel<<<PACK_TOTAL / 256, 256>>>(
        x, wq, wk, wv, wo, bq, bk, bv, x2, wqkv2, wo2, bias3);

    // ---- fused QKV projection ----
    dim3 gQKV(3 * D_ / 128, M_ / 128);     // 12 x 128
    gemm_qkv_kernel<<<gQKV, 256, gemm_smem>>>(x2, wqkv2, bias3, q2, k2, v2);

    dim3 gT(T_ * B_ * H_, N_ / 32);        // 128 x 32
    transpose_v_kernel<<<gT, 128>>>(v2, v2t);

    dim3 gAttn(N_ / 64, T_ * B_ * H_);     // 16 x 128
    attn_bf16_kernel<<<gAttn, 128, attn_smem>>>(q2, k2, v2t, x2);  // ctx -> x2

    dim3 gO(D_ / 128, M_ / 128);           // 4 x 128
    gemm_o_kernel<<<gO, 256, gemm_smem>>>(x2, wo2, bo, out);
}

// round 14
// speedup vs baseline: 1.5682x; 1.5682x over previous
#include <cuda_runtime.h>
#include <cuda_bf16.h>
#include <cstdint>

// Problem constants
#define T_  4
#define B_  4
#define N_  1024
#define D_  512
#define H_  8
#define HD_ 64
#define M_  (T_*B_*N_)     // 16384 rows
#define ROWU 512           // packed row width in u32: [hi 256][mid 256]

// Scratch (no cudaMalloc). Packed bf16 (hi,mid) plane buffers, u32 units.
__device__ uint32_t gU_x2  [(size_t)M_*ROWU];   // x packed; reused as ctx packed
__device__ uint32_t gU_q2  [(size_t)M_*ROWU];
__device__ uint32_t gU_k2  [(size_t)M_*ROWU];
__device__ uint32_t gU_v2  [(size_t)M_*ROWU];
__device__ uint32_t gU_v2t [(size_t)M_*ROWU];   // V transposed per head
__device__ uint32_t gU_wqkv2[(size_t)3*D_*ROWU]; // wq|wk|wv packed, rows 0..1535
__device__ uint32_t gU_wo2 [(size_t)D_*ROWU];
__device__ float    g_bias3[3*D_];               // bq|bk|bv

// ---------------------------------------------------------------------------
// bf16 split + mma + ldmatrix helpers
// ---------------------------------------------------------------------------
__device__ __forceinline__ uint32_t bpack(__nv_bfloat16 a, __nv_bfloat16 b) {
    return (uint32_t)__bfloat16_as_ushort(a) |
           ((uint32_t)__bfloat16_as_ushort(b) << 16);
}
__device__ __forceinline__ void split2(float x0, float x1,
                                       uint32_t& hi, uint32_t& mid) {
    __nv_bfloat16 h0 = __float2bfloat16(x0);
    __nv_bfloat16 h1 = __float2bfloat16(x1);
    __nv_bfloat16 m0 = __float2bfloat16(x0 - __bfloat162float(h0));
    __nv_bfloat16 m1 = __float2bfloat16(x1 - __bfloat162float(h1));
    hi = bpack(h0, h1); mid = bpack(m0, m1);
}
__device__ __forceinline__ void mma_bf16(float c[4], const uint32_t a[4],
                                         uint32_t b0, uint32_t b1) {
    asm volatile(
        "mma.sync.aligned.m16n8k16.row.col.f32.bf16.bf16.f32 "
        "{%0,%1,%2,%3}, {%4,%5,%6,%7}, {%8,%9}, {%0,%1,%2,%3};"
        : "+f"(c[0]), "+f"(c[1]), "+f"(c[2]), "+f"(c[3])
        : "r"(a[0]), "r"(a[1]), "r"(a[2]), "r"(a[3]), "r"(b0), "r"(b1));
}
__device__ __forceinline__ void mma3b(float c[4],
                                      const uint32_t ah[4], const uint32_t am[4],
                                      uint32_t bh0, uint32_t bh1,
                                      uint32_t bm0, uint32_t bm1) {
    mma_bf16(c, ah, bh0, bh1);
    mma_bf16(c, ah, bm0, bm1);
    mma_bf16(c, am, bh0, bh1);
}
__device__ __forceinline__ void ldm_x4(uint32_t& r0, uint32_t& r1,
                                       uint32_t& r2, uint32_t& r3, uint32_t addr) {
    asm volatile("ldmatrix.sync.aligned.m8n8.x4.shared.b16 {%0,%1,%2,%3}, [%4];"
                 : "=r"(r0), "=r"(r1), "=r"(r2), "=r"(r3) : "r"(addr));
}
__device__ __forceinline__ void cpa16(uint32_t saddr, const void* gptr) {
    asm volatile("cp.async.cg.shared.global [%0], [%1], 16;\n"
                 :: "r"(saddr), "l"(gptr));
}
__device__ __forceinline__ uint32_t s2u(const void* p) {
    return (uint32_t)__cvta_generic_to_shared(p);
}

// ---------------------------------------------------------------------------
// Fused pack: one launch packs x + wq/wk/wv (-> wqkv2) + wo (-> wo2)
// ---------------------------------------------------------------------------
#define XQ_ (M_*128)
#define WQ_ (D_*128)
#define PACK_TOTAL (XQ_ + 4*WQ_)

__global__ void pack_all_kernel(
    const float* __restrict__ x,
    const float* __restrict__ wq, const float* __restrict__ wk,
    const float* __restrict__ wv, const float* __restrict__ wo,
    const float* __restrict__ bq, const float* __restrict__ bk,
    const float* __restrict__ bv,
    uint32_t* __restrict__ x2, uint32_t* __restrict__ wqkv2,
    uint32_t* __restrict__ wo2, float* __restrict__ bias3)
{
    int q = blockIdx.x * blockDim.x + threadIdx.x;
    if (q < 3 * D_)
        bias3[q] = (q < D_) ? bq[q] : (q < 2*D_) ? bk[q - D_] : bv[q - 2*D_];
    if (q >= PACK_TOTAL) return;

    const float* src; uint32_t* dst; int j;
    if (q < XQ_) { src = x; dst = x2; j = q; }
    else {
        int w = (q - XQ_) >> 16;           // WQ_ = 65536
        j = (q - XQ_) & 65535;
        src = (w == 0) ? wq : (w == 1) ? wk : (w == 2) ? wv : wo;
        dst = (w < 3) ? wqkv2 + (size_t)w * D_ * ROWU : wo2;
    }
    float4 s = ((const float4*)src)[j];
    int p = 2 * j, r = p >> 8, c = p & 255;
    uint32_t h0, m0, h1, m1;
    split2(s.x, s.y, h0, m0);
    split2(s.z, s.w, h1, m1);
    *(uint2*)&dst[(size_t)r * ROWU + c]       = make_uint2(h0, h1);
    *(uint2*)&dst[(size_t)r * ROWU + 256 + c] = make_uint2(m0, m1);
}

// ---------------------------------------------------------------------------
// V transpose: v2 [tok][ch planes] -> v2t [head][ch][hi 512 | mid 512]
// ---------------------------------------------------------------------------
__global__ void transpose_v_kernel(const uint32_t* __restrict__ v2,
                                   uint32_t* __restrict__ v2t)
{
    __shared__ uint32_t ts[32][65];

    const int head = blockIdx.x;
    const int h    = head & (H_ - 1);
    const int tb   = head >> 3;
    const int k0   = blockIdx.y * 32;
    const int tokb = tb * N_ + k0;

    for (int i = threadIdx.x; i < 32 * 64; i += 128) {
        int tok = i >> 6, c = i & 63;
        size_t src = (size_t)(tokb + tok) * ROWU + h * 32 +
                     (c < 32 ? c : 256 + (c - 32));
        ts[tok][c] = v2[src];
    }
    __syncthreads();

    const size_t outb = (size_t)head * (64 * 1024);
    for (int i = threadIdx.x; i < 64 * 32; i += 128) {
        int ch = i >> 5, rest = i & 31;
        int plane = rest >> 4, j = rest & 15;
        uint32_t w0 = ts[2 * j    ][plane * 32 + (ch >> 1)];
        uint32_t w1 = ts[2 * j + 1][plane * 32 + (ch >> 1)];
        uint16_t e0 = (ch & 1) ? (uint16_t)(w0 >> 16) : (uint16_t)(w0 & 0xffff);
        uint16_t e1 = (ch & 1) ? (uint16_t)(w1 >> 16) : (uint16_t)(w1 & 0xffff);
        v2t[outb + (size_t)ch * 1024 + plane * 512 + (k0 >> 1) + j] =
            (uint32_t)e0 | ((uint32_t)e1 << 16);
    }
}

// ---------------------------------------------------------------------------
// GEMM common (EXACT round-10 shape): block 128x128, 256 thr (4Mx2N warps),
// 2-stage cp.async, wait -> sync -> compute -> sync -> refill.
// ldmatrix operand fetch. Smem chunk row: [hi 16 u32][mid 16][pad 4] = 36.
// ---------------------------------------------------------------------------
#define GSTR  36
#define GSTG  (128*GSTR)
#define NCHUNK 16

#define GEMM_PROLOG(A2PTR, W2PTR)                                              \
    extern __shared__ uint32_t smg[];                                          \
    uint32_t* Abuf[2] = { smg,            smg + GSTG };                        \
    uint32_t* Wbuf[2] = { smg + 2*GSTG,   smg + 3*GSTG };                      \
    const int tid  = threadIdx.x;                                              \
    const int lane = tid & 31, warp = tid >> 5;                                \
    const int g    = lane >> 2, tg = lane & 3;                                 \
    const int wm   = (warp >> 1) * 32;                                         \
    const int wn   = (warp & 1) * 64;                                          \
    const int mb   = blockIdx.y * 128, nb = blockIdx.x * 128;                  \
    const uint32_t aOff = (uint32_t)((wm + (lane & 15)) * GSTR + (lane >> 4) * 4); \
    const uint32_t wOff = (uint32_t)((wn + (lane & 7)) * GSTR +                \
                                     ((lane >> 3) & 1) * 4 +                   \
                                     (lane >> 4) * 8 * GSTR);                  \
    auto load_stage = [&](int t, int buf) {                                    \
        _Pragma("unroll")                                                      \
        for (int l = tid; l < 1024; l += 256) {                                \
            int r = l >> 3, part = l & 7;                                      \
            size_t src; uint32_t dst;                                          \
            if (part < 4) {                                                    \
                src = (size_t)(mb + r) * ROWU + 16 * t + 4 * part;             \
                dst = s2u(&Abuf[buf][r * GSTR + 4 * part]);                    \
            } else {                                                           \
                src = (size_t)(mb + r) * ROWU + 256 + 16 * t + 4 * (part - 4); \
                dst = s2u(&Abuf[buf][r * GSTR + 16 + 4 * (part - 4)]);         \
            }                                                                  \
            cpa16(dst, &(A2PTR)[src]);                                         \
        }                                                                      \
        _Pragma("unroll")                                                      \
        for (int l = tid; l < 1024; l += 256) {                                \
            int r = l >> 3, part = l & 7;                                      \
            size_t src; uint32_t dst;                                          \
            if (part < 4) {                                                    \
                src = (size_t)(nb + r) * ROWU + 16 * t + 4 * part;             \
                dst = s2u(&Wbuf[buf][r * GSTR + 4 * part]);                    \
            } else {                                                           \
                src = (size_t)(nb + r) * ROWU + 256 + 16 * t + 4 * (part - 4); \
                dst = s2u(&Wbuf[buf][r * GSTR + 16 + 4 * (part - 4)]);         \
            }                                                                  \
            cpa16(dst, &(W2PTR)[src]);                                         \
        }                                                                      \
    };                                                                         \
    float acc[2][8][4];                                                        \
    _Pragma("unroll")                                                          \
    for (int i = 0; i < 2; i++)                                                \
        _Pragma("unroll")                                                      \
        for (int j = 0; j < 8; j++)                                            \
            _Pragma("unroll")                                                  \
            for (int l = 0; l < 4; l++) acc[i][j][l] = 0.f;                    \
    load_stage(0, 0);                                                          \
    asm volatile("cp.async.commit_group;\n" ::: "memory");                     \
    load_stage(1, 1);                                                          \
    asm volatile("cp.async.commit_group;\n" ::: "memory");                     \
    for (int t = 0; t < NCHUNK; t++) {                                         \
        const int buf = t & 1;                                                 \
        asm volatile("cp.async.wait_group 1;\n" ::: "memory");                 \
        __syncthreads();                                                       \
        const uint32_t aBase = s2u(Abuf[buf]) + 4 * aOff;                      \
        const uint32_t wBase = s2u(Wbuf[buf]) + 4 * wOff;                      \
        _Pragma("unroll")                                                      \
        for (int s = 0; s < 2; s++) {                                          \
            uint32_t ah[2][4], am[2][4];                                       \
            _Pragma("unroll")                                                  \
            for (int mi = 0; mi < 2; mi++) {                                   \
                ldm_x4(ah[mi][0], ah[mi][1], ah[mi][2], ah[mi][3],             \
                       aBase + 4 * (16 * mi * GSTR + 8 * s));                  \
                ldm_x4(am[mi][0], am[mi][1], am[mi][2], am[mi][3],             \
                       aBase + 4 * (16 * mi * GSTR + 16 + 8 * s));             \
            }                                                                  \
            _Pragma("unroll")                                                  \
            for (int njp = 0; njp < 4; njp++) {                                \
                uint32_t bh0, bh1, bh2, bh3, bm0, bm1, bm2, bm3;               \
                ldm_x4(bh0, bh1, bh2, bh3,                                     \
                       wBase + 4 * (16 * njp * GSTR + 8 * s));                 \
                ldm_x4(bm0, bm1, bm2, bm3,                                     \
                       wBase + 4 * (16 * njp * GSTR + 16 + 8 * s));            \
                mma3b(acc[0][2*njp    ], ah[0], am[0], bh0, bh1, bm0, bm1);    \
                mma3b(acc[1][2*njp    ], ah[1], am[1], bh0, bh1, bm0, bm1);    \
                mma3b(acc[0][2*njp + 1], ah[0], am[0], bh2, bh3, bm2, bm3);    \
                mma3b(acc[1][2*njp + 1], ah[1], am[1], bh2, bh3, bm2, bm3);    \
            }                                                                  \
        }                                                                      \
        __syncthreads();                                                       \
        if (t + 2 < NCHUNK) load_stage(t + 2, buf);                            \
        asm volatile("cp.async.commit_group;\n" ::: "memory");                 \
    }

// ---------------------------------------------------------------------------
// Fused QKV GEMM: W = wqkv2 (1536 rows), bias3 concat, split-packed output
// routed to q2/k2/v2 by column segment. Grid (12, 128).
// ---------------------------------------------------------------------------
__global__ __launch_bounds__(256, 2) void gemm_qkv_kernel(
    const uint32_t* __restrict__ A2, const uint32_t* __restrict__ W2,
    const float* __restrict__ bias3,
    uint32_t* __restrict__ q2, uint32_t* __restrict__ k2,
    uint32_t* __restrict__ v2)
{
    GEMM_PROLOG(A2, W2)

    const int seg = nb >> 9;                       // 0=q,1=k,2=v (const/block)
    uint32_t* C = (seg == 0) ? q2 : (seg == 1) ? k2 : v2;

    #pragma unroll
    for (int mi = 0; mi < 2; mi++) {
        int r0 = mb + wm + mi * 16 + g;
        #pragma unroll
        for (int nj = 0; nj < 8; nj++) {
            int c0g = nb + wn + nj * 8 + 2 * tg;   // global col in [0,1536)
            int c0  = c0g & 511;                   // col within segment
            float bia0 = bias3[c0g], bia1 = bias3[c0g + 1];
            float v00 = acc[mi][nj][0] + bia0;
            float v01 = acc[mi][nj][1] + bia1;
            float v10 = acc[mi][nj][2] + bia0;
            float v11 = acc[mi][nj][3] + bia1;
            uint32_t hi, mid;
            split2(v00, v01, hi, mid);
            C[(size_t)r0 * ROWU + (c0 >> 1)]       = hi;
            C[(size_t)r0 * ROWU + 256 + (c0 >> 1)] = mid;
            split2(v10, v11, hi, mid);
            C[(size_t)(r0 + 8) * ROWU + (c0 >> 1)]       = hi;
            C[(size_t)(r0 + 8) * ROWU + 256 + (c0 >> 1)] = mid;
        }
    }
}

// ---------------------------------------------------------------------------
// O projection GEMM: plain float output. Grid (4, 128).
// ---------------------------------------------------------------------------
__global__ __launch_bounds__(256, 2) void gemm_o_kernel(
    const uint32_t* __restrict__ A2, const uint32_t* __restrict__ W2,
    const float* __restrict__ bias, float* __restrict__ C)
{
    GEMM_PROLOG(A2, W2)

    #pragma unroll
    for (int mi = 0; mi < 2; mi++) {
        int r0 = mb + wm + mi * 16 + g;
        #pragma unroll
        for (int nj = 0; nj < 8; nj++) {
            int c0 = nb + wn + nj * 8 + 2 * tg;
            float bia0 = bias[c0], bia1 = bias[c0 + 1];
            *(float2*)&C[(size_t)r0 * D_ + c0] =
                make_float2(acc[mi][nj][0] + bia0, acc[mi][nj][1] + bia1);
            *(float2*)&C[(size_t)(r0 + 8) * D_ + c0] =
                make_float2(acc[mi][nj][2] + bia0, acc[mi][nj][3] + bia1);
        }
    }
}

// ---------------------------------------------------------------------------
// bf16-split attention — round-10 mainloop shape (wait_group 2, two syncs,
// refill after compute), but 256 threads / 8 warps per CTA: 128 queries
// share each K/V tile, halving cp.async traffic per query.
// Each warp still owns 16 q-rows x all 32 keys -> in-lane S->P->PV.
// ---------------------------------------------------------------------------
#define KSTR 68
#define VSTR 36
#define KTILE (32*KSTR)
#define VTILE (64*VSTR)
#define NSTAGE 3
#define NTILES (N_/32)
#define ATHR 256

__global__ __launch_bounds__(ATHR, 2) void attn_bf16_kernel(
    const uint32_t* __restrict__ q2, const uint32_t* __restrict__ k2,
    const uint32_t* __restrict__ v2t, uint32_t* __restrict__ ctx2)
{
    extern __shared__ uint32_t sma[];
    uint32_t* Kb[NSTAGE];
    uint32_t* Vb[NSTAGE];
    #pragma unroll
    for (int i = 0; i < NSTAGE; i++) {
        Kb[i] = sma + i * KTILE;
        Vb[i] = sma + NSTAGE * KTILE + i * VTILE;
    }

    const int tid  = threadIdx.x;
    const int lane = tid & 31, warp = tid >> 5;
    const int g    = lane >> 2, tg = lane & 3;
    const int wm   = warp * 16;                 // 0..112 (8 warps)

    const int hidx = blockIdx.y;
    const int h    = hidx & (H_ - 1);
    const int tb   = hidx >> 3;
    const int tokb = tb * N_;
    const size_t headv = (size_t)hidx * (64 * 1024);
    const int q0   = blockIdx.x * 128;          // 128 queries per CTA

    const uint32_t kOff = (uint32_t)((lane & 7) * KSTR +
                                     ((lane >> 3) & 1) * 4 +
                                     (lane >> 4) * 8 * KSTR);
    const uint32_t vOff = (uint32_t)((lane & 7) * VSTR +
                                     ((lane >> 3) & 1) * 4 +
                                     (lane >> 4) * 8 * VSTR);

    auto load_tile = [&](int t, int buf) {
        const int k0 = 32 * t;
        #pragma unroll
        for (int l = tid; l < 512; l += ATHR) {   // K: 32 keys x 64 u32
            int key = l >> 4, part = l & 15;
            size_t rowb = (size_t)(tokb + k0 + key) * ROWU + h * 32;
            size_t src; uint32_t dst;
            if (part < 8) {
                src = rowb + 4 * part;
                dst = s2u(&Kb[buf][key * KSTR + 4 * part]);
            } else {
                src = rowb + 256 + 4 * (part - 8);
                dst = s2u(&Kb[buf][key * KSTR + 32 + 4 * (part - 8)]);
            }
            cpa16(dst, &k2[src]);
        }
        #pragma unroll
        for (int l = tid; l < 512; l += ATHR) {   // Vt: 64 ch x 32 u32
            int ch = l >> 3, part = l & 7;
            size_t vrow = headv + (size_t)ch * 1024;
            size_t src; uint32_t dst;
            if (part < 4) {
                src = vrow + (k0 >> 1) + 4 * part;
                dst = s2u(&Vb[buf][ch * VSTR + 4 * part]);
            } else {
                src = vrow + 512 + (k0 >> 1) + 4 * (part - 4);
                dst = s2u(&Vb[buf][ch * VSTR + 16 + 4 * (part - 4)]);
            }
            cpa16(dst, &v2t[src]);
        }
    };

    #pragma unroll
    for (int p = 0; p < NSTAGE; p++) {
        load_tile(p, p);
        asm volatile("cp.async.commit_group;\n" ::: "memory");
    }

    // ---- Q fragments -> registers ----
    uint32_t qh[4][4], qm[4][4];
    {
        size_t rA = (size_t)(tokb + q0 + wm + g) * ROWU + h * 32;
        size_t rB = rA + (size_t)8 * ROWU;
        #pragma unroll
        for (int s = 0; s < 4; s++) {
            qh[s][0] = q2[rA + 8*s + tg];        qh[s][1] = q2[rB + 8*s + tg];
            qh[s][2] = q2[rA + 8*s + tg + 4];    qh[s][3] = q2[rB + 8*s + tg + 4];
            qm[s][0] = q2[rA + 256 + 8*s + tg];      qm[s][1] = q2[rB + 256 + 8*s + tg];
            qm[s][2] = q2[rA + 256 + 8*s + tg + 4];  qm[s][3] = q2[rB + 256 + 8*s + tg + 4];
        }
    }

    float accPV[8][4];
    #pragma unroll
    for (int j = 0; j < 8; j++)
        #pragma unroll
        for (int l = 0; l < 4; l++) accPV[j][l] = 0.f;
    float dA = 0.f, dB = 0.f;

    int buf = 0;
    for (int t = 0; t < NTILES; t++) {
        asm volatile("cp.async.wait_group 2;\n" ::: "memory");
        __syncthreads();

        const uint32_t kBase = s2u(Kb[buf]) + 4 * kOff;
        const uint32_t vBase = s2u(Vb[buf]) + 4 * vOff;

        // ---- S = Q K^T : 16 rows x 32 keys ----
        float accS[4][4];
        #pragma unroll
        for (int j = 0; j < 4; j++)
            #pragma unroll
            for (int l = 0; l < 4; l++) accS[j][l] = 0.f;

        #pragma unroll
        for (int s = 0; s < 4; s++) {
            #pragma unroll
            for (int njp = 0; njp < 2; njp++) {
                uint32_t bh0, bh1, bh2, bh3, bm0, bm1, bm2, bm3;
                ldm_x4(bh0, bh1, bh2, bh3,
                       kBase + 4 * (16 * njp * KSTR + 8 * s));
                ldm_x4(bm0, bm1, bm2, bm3,
                       kBase + 4 * (16 * njp * KSTR + 32 + 8 * s));
                mma3b(accS[2*njp    ], qh[s], qm[s], bh0, bh1, bm0, bm1);
                mma3b(accS[2*njp + 1], qh[s], qm[s], bh2, bh3, bm2, bm3);
            }
        }

        // ---- P = relu(S/8) in-lane -> A frags; denom; PV ----
        #pragma unroll
        for (int kb = 0; kb < 2; kb++) {
            float p0 = fmaxf(accS[2*kb    ][0] * 0.125f, 0.f);
            float p1 = fmaxf(accS[2*kb    ][1] * 0.125f, 0.f);
            float p2 = fmaxf(accS[2*kb    ][2] * 0.125f, 0.f);
            float p3 = fmaxf(accS[2*kb    ][3] * 0.125f, 0.f);
            float p4 = fmaxf(accS[2*kb + 1][0] * 0.125f, 0.f);
            float p5 = fmaxf(accS[2*kb + 1][1] * 0.125f, 0.f);
            float p6 = fmaxf(accS[2*kb + 1][2] * 0.125f, 0.f);
            float p7 = fmaxf(accS[2*kb + 1][3] * 0.125f, 0.f);
            dA += p0 + p1 + p4 + p5;
            dB += p2 + p3 + p6 + p7;

            uint32_t ah[4], am[4];
            split2(p0, p1, ah[0], am[0]);
            split2(p2, p3, ah[1], am[1]);
            split2(p4, p5, ah[2], am[2]);
            split2(p6, p7, ah[3], am[3]);

            #pragma unroll
            for (int njp = 0; njp < 4; njp++) {
                uint32_t bh0, bh1, bh2, bh3, bm0, bm1, bm2, bm3;
                ldm_x4(bh0, bh1, bh2, bh3,
                       vBase + 4 * (16 * njp * VSTR + 8 * kb));
                ldm_x4(bm0, bm1, bm2, bm3,
                       vBase + 4 * (16 * njp * VSTR + 16 + 8 * kb));
                mma3b(accPV[2*njp    ], ah, am, bh0, bh1, bm0, bm1);
                mma3b(accPV[2*njp + 1], ah, am, bh2, bh3, bm2, bm3);
            }
        }
        __syncthreads();   // all warps done with buf before refill

        if (t + NSTAGE < NTILES) load_tile(t + NSTAGE, buf);
        asm volatile("cp.async.commit_group;\n" ::: "memory");

        buf = (buf == NSTAGE - 1) ? 0 : buf + 1;
    }

    // ---- denominator reduce over tg lanes ----
    dA += __shfl_xor_sync(0xffffffffu, dA, 1);
    dA += __shfl_xor_sync(0xffffffffu, dA, 2);
    dB += __shfl_xor_sync(0xffffffffu, dB, 1);
    dB += __shfl_xor_sync(0xffffffffu, dB, 2);
    const float invA = 1.f / (dA + 1e-6f);
    const float invB = 1.f / (dB + 1e-6f);

    // ---- write ctx packed (planes) for O projection ----
    size_t rA = (size_t)(tokb + q0 + wm + g) * ROWU + h * 32;
    size_t rB = rA + (size_t)8 * ROWU;
    #pragma unroll
    for (int nj = 0; nj < 8; nj++) {
        uint32_t hi, mid;
        split2(accPV[nj][0] * invA, accPV[nj][1] * invA, hi, mid);
        ctx2[rA + 4*nj + tg]       = hi;
        ctx2[rA + 256 + 4*nj + tg] = mid;
        split2(accPV[nj][2] * invB, accPV[nj][3] * invB, hi, mid);
        ctx2[rB + 4*nj + tg]       = hi;
        ctx2[rB + 256 + 4*nj + tg] = mid;
    }
}

// ---------------------------------------------------------------------------
// Launcher. Input order: x, wq, bq, wk, bk, wv, bv, wo, bo
// ---------------------------------------------------------------------------
extern "C" void kernel_launch(void* const* d_in, const int* in_sizes, int n_in,
                              void* d_out, int out_size)
{
    const float* x  = (const float*)d_in[0];
    const float* wq = (const float*)d_in[1];
    const float* bq = (const float*)d_in[2];
    const float* wk = (const float*)d_in[3];
    const float* bk = (const float*)d_in[4];
    const float* wv = (const float*)d_in[5];
    const float* bv = (const float*)d_in[6];
    const float* wo = (const float*)d_in[7];
    const float* bo = (const float*)d_in[8];
    float* out = (float*)d_out;

    uint32_t *x2, *q2, *k2, *v2, *v2t, *wqkv2, *wo2;
    float* bias3;
    cudaGetSymbolAddress((void**)&x2,    gU_x2);
    cudaGetSymbolAddress((void**)&q2,    gU_q2);
    cudaGetSymbolAddress((void**)&k2,    gU_k2);
    cudaGetSymbolAddress((void**)&v2,    gU_v2);
    cudaGetSymbolAddress((void**)&v2t,   gU_v2t);
    cudaGetSymbolAddress((void**)&wqkv2, gU_wqkv2);
    cudaGetSymbolAddress((void**)&wo2,   gU_wo2);
    cudaGetSymbolAddress((void**)&bias3, g_bias3);

    const int gemm_smem = 4 * GSTG * (int)sizeof(uint32_t);                 // 73,728 B
    const int attn_smem = NSTAGE * (KTILE + VTILE) * (int)sizeof(uint32_t); // 53,760 B
    cudaFuncSetAttribute(gemm_qkv_kernel,
        cudaFuncAttributeMaxDynamicSharedMemorySize, gemm_smem);
    cudaFuncSetAttribute(gemm_o_kernel,
        cudaFuncAttributeMaxDynamicSharedMemorySize, gemm_smem);
    cudaFuncSetAttribute(attn_bf16_kernel,
        cudaFuncAttributeMaxDynamicSharedMemorySize, attn_smem);

    // ---- fused pack (x + 4 weights + bias concat) ----
    pack_all_kernel<<<PACK_TOTAL / 256, 256>>>(
        x, wq, wk, wv, wo, bq, bk, bv, x2, wqkv2, wo2, bias3);

    // ---- fused QKV projection ----
    dim3 gQKV(3 * D_ / 128, M_ / 128);     // 12 x 128
    gemm_qkv_kernel<<<gQKV, 256, gemm_smem>>>(x2, wqkv2, bias3, q2, k2, v2);

    dim3 gT(T_ * B_ * H_, N_ / 32);        // 128 x 32
    transpose_v_kernel<<<gT, 128>>>(v2, v2t);

    dim3 gAttn(N_ / 128, T_ * B_ * H_);    // 8 x 128
    attn_bf16_kernel<<<gAttn, ATHR, attn_smem>>>(q2, k2, v2t, x2);  // ctx -> x2

    dim3 gO(D_ / 128, M_ / 128);           // 4 x 128
    gemm_o_kernel<<<gO, 256, gemm_smem>>>(x2, wo2, bo, out);
}

// round 16
// speedup vs baseline: 1.6711x; 1.0656x over previous
#include <cuda_runtime.h>
#include <cuda_bf16.h>
#include <cstdint>

// Problem constants
#define T_  4
#define B_  4
#define N_  1024
#define D_  512
#define H_  8
#define HD_ 64
#define M_  (T_*B_*N_)     // 16384 rows
#define ROWU 512           // packed row width in u32: [hi 256][mid 256]

// Scratch (no cudaMalloc). Packed bf16 (hi,mid) plane buffers, u32 units.
__device__ uint32_t gU_x2  [(size_t)M_*ROWU];   // x packed; reused as ctx packed
__device__ uint32_t gU_q2  [(size_t)M_*ROWU];
__device__ uint32_t gU_k2  [(size_t)M_*ROWU];
__device__ uint32_t gU_v2  [(size_t)M_*ROWU];
__device__ uint32_t gU_wqkv2[(size_t)3*D_*ROWU]; // wq|wk|wv packed, rows 0..1535
__device__ uint32_t gU_wo2 [(size_t)D_*ROWU];
__device__ float    g_bias3[3*D_];               // bq|bk|bv

// ---------------------------------------------------------------------------
// bf16 split + mma + ldmatrix helpers
// ---------------------------------------------------------------------------
__device__ __forceinline__ uint32_t bpack(__nv_bfloat16 a, __nv_bfloat16 b) {
    return (uint32_t)__bfloat16_as_ushort(a) |
           ((uint32_t)__bfloat16_as_ushort(b) << 16);
}
__device__ __forceinline__ void split2(float x0, float x1,
                                       uint32_t& hi, uint32_t& mid) {
    __nv_bfloat16 h0 = __float2bfloat16(x0);
    __nv_bfloat16 h1 = __float2bfloat16(x1);
    __nv_bfloat16 m0 = __float2bfloat16(x0 - __bfloat162float(h0));
    __nv_bfloat16 m1 = __float2bfloat16(x1 - __bfloat162float(h1));
    hi = bpack(h0, h1); mid = bpack(m0, m1);
}
__device__ __forceinline__ void mma_bf16(float c[4], const uint32_t a[4],
                                         uint32_t b0, uint32_t b1) {
    asm volatile(
        "mma.sync.aligned.m16n8k16.row.col.f32.bf16.bf16.f32 "
        "{%0,%1,%2,%3}, {%4,%5,%6,%7}, {%8,%9}, {%0,%1,%2,%3};"
        : "+f"(c[0]), "+f"(c[1]), "+f"(c[2]), "+f"(c[3])
        : "r"(a[0]), "r"(a[1]), "r"(a[2]), "r"(a[3]), "r"(b0), "r"(b1));
}
__device__ __forceinline__ void mma3b(float c[4],
                                      const uint32_t ah[4], const uint32_t am[4],
                                      uint32_t bh0, uint32_t bh1,
                                      uint32_t bm0, uint32_t bm1) {
    mma_bf16(c, ah, bh0, bh1);
    mma_bf16(c, ah, bm0, bm1);
    mma_bf16(c, am, bh0, bh1);
}
__device__ __forceinline__ void ldm_x4(uint32_t& r0, uint32_t& r1,
                                       uint32_t& r2, uint32_t& r3, uint32_t addr) {
    asm volatile("ldmatrix.sync.aligned.m8n8.x4.shared.b16 {%0,%1,%2,%3}, [%4];"
                 : "=r"(r0), "=r"(r1), "=r"(r2), "=r"(r3) : "r"(addr));
}
__device__ __forceinline__ void ldm_x4t(uint32_t& r0, uint32_t& r1,
                                        uint32_t& r2, uint32_t& r3, uint32_t addr) {
    asm volatile("ldmatrix.sync.aligned.m8n8.x4.trans.shared.b16 {%0,%1,%2,%3}, [%4];"
                 : "=r"(r0), "=r"(r1), "=r"(r2), "=r"(r3) : "r"(addr));
}
__device__ __forceinline__ void cpa16(uint32_t saddr, const void* gptr) {
    asm volatile("cp.async.cg.shared.global [%0], [%1], 16;\n"
                 :: "r"(saddr), "l"(gptr));
}
__device__ __forceinline__ uint32_t s2u(const void* p) {
    return (uint32_t)__cvta_generic_to_shared(p);
}

// ---------------------------------------------------------------------------
// Fused pack: one launch packs x + wq/wk/wv (-> wqkv2) + wo (-> wo2)
// ---------------------------------------------------------------------------
#define XQ_ (M_*128)
#define WQ_ (D_*128)
#define PACK_TOTAL (XQ_ + 4*WQ_)

__global__ void pack_all_kernel(
    const float* __restrict__ x,
    const float* __restrict__ wq, const float* __restrict__ wk,
    const float* __restrict__ wv, const float* __restrict__ wo,
    const float* __restrict__ bq, const float* __restrict__ bk,
    const float* __restrict__ bv,
    uint32_t* __restrict__ x2, uint32_t* __restrict__ wqkv2,
    uint32_t* __restrict__ wo2, float* __restrict__ bias3)
{
    int q = blockIdx.x * blockDim.x + threadIdx.x;
    if (q < 3 * D_)
        bias3[q] = (q < D_) ? bq[q] : (q < 2*D_) ? bk[q - D_] : bv[q - 2*D_];
    if (q >= PACK_TOTAL) return;

    const float* src; uint32_t* dst; int j;
    if (q < XQ_) { src = x; dst = x2; j = q; }
    else {
        int w = (q - XQ_) >> 16;           // WQ_ = 65536
        j = (q - XQ_) & 65535;
        src = (w == 0) ? wq : (w == 1) ? wk : (w == 2) ? wv : wo;
        dst = (w < 3) ? wqkv2 + (size_t)w * D_ * ROWU : wo2;
    }
    float4 s = ((const float4*)src)[j];
    int p = 2 * j, r = p >> 8, c = p & 255;
    uint32_t h0, m0, h1, m1;
    split2(s.x, s.y, h0, m0);
    split2(s.z, s.w, h1, m1);
    *(uint2*)&dst[(size_t)r * ROWU + c]       = make_uint2(h0, h1);
    *(uint2*)&dst[(size_t)r * ROWU + 256 + c] = make_uint2(m0, m1);
}

// ---------------------------------------------------------------------------
// GEMM common (round-10 shape): block 128x128, 256 thr (4Mx2N warps),
// 2-stage cp.async, wait -> sync -> compute -> sync -> refill.
// ldmatrix operand fetch. Smem chunk row: [hi 16 u32][mid 16][pad 4] = 36.
// ---------------------------------------------------------------------------
#define GSTR  36
#define GSTG  (128*GSTR)
#define NCHUNK 16

#define GEMM_PROLOG(A2PTR, W2PTR)                                              \
    extern __shared__ uint32_t smg[];                                          \
    uint32_t* Abuf[2] = { smg,            smg + GSTG };                        \
    uint32_t* Wbuf[2] = { smg + 2*GSTG,   smg + 3*GSTG };                      \
    const int tid  = threadIdx.x;                                              \
    const int lane = tid & 31, warp = tid >> 5;                                \
    const int g    = lane >> 2, tg = lane & 3;                                 \
    const int wm   = (warp >> 1) * 32;                                         \
    const int wn   = (warp & 1) * 64;                                          \
    const int mb   = blockIdx.y * 128, nb = blockIdx.x * 128;                  \
    const uint32_t aOff = (uint32_t)((wm + (lane & 15)) * GSTR + (lane >> 4) * 4); \
    const uint32_t wOff = (uint32_t)((wn + (lane & 7)) * GSTR +                \
                                     ((lane >> 3) & 1) * 4 +                   \
                                     (lane >> 4) * 8 * GSTR);                  \
    auto load_stage = [&](int t, int buf) {                                    \
        _Pragma("unroll")                                                      \
        for (int l = tid; l < 1024; l += 256) {                                \
            int r = l >> 3, part = l & 7;                                      \
            size_t src; uint32_t dst;                                          \
            if (part < 4) {                                                    \
                src = (size_t)(mb + r) * ROWU + 16 * t + 4 * part;             \
                dst = s2u(&Abuf[buf][r * GSTR + 4 * part]);                    \
            } else {                                                           \
                src = (size_t)(mb + r) * ROWU + 256 + 16 * t + 4 * (part - 4); \
                dst = s2u(&Abuf[buf][r * GSTR + 16 + 4 * (part - 4)]);         \
            }                                                                  \
            cpa16(dst, &(A2PTR)[src]);                                         \
        }                                                                      \
        _Pragma("unroll")                                                      \
        for (int l = tid; l < 1024; l += 256) {                                \
            int r = l >> 3, part = l & 7;                                      \
            size_t src; uint32_t dst;                                          \
            if (part < 4) {                                                    \
                src = (size_t)(nb + r) * ROWU + 16 * t + 4 * part;             \
                dst = s2u(&Wbuf[buf][r * GSTR + 4 * part]);                    \
            } else {                                                           \
                src = (size_t)(nb + r) * ROWU + 256 + 16 * t + 4 * (part - 4); \
                dst = s2u(&Wbuf[buf][r * GSTR + 16 + 4 * (part - 4)]);         \
            }                                                                  \
            cpa16(dst, &(W2PTR)[src]);                                         \
        }                                                                      \
    };                                                                         \
    float acc[2][8][4];                                                        \
    _Pragma("unroll")                                                          \
    for (int i = 0; i < 2; i++)                                                \
        _Pragma("unroll")                                                      \
        for (int j = 0; j < 8; j++)                                            \
            _Pragma("unroll")                                                  \
            for (int l = 0; l < 4; l++) acc[i][j][l] = 0.f;                    \
    load_stage(0, 0);                                                          \
    asm volatile("cp.async.commit_group;\n" ::: "memory");                     \
    load_stage(1, 1);                                                          \
    asm volatile("cp.async.commit_group;\n" ::: "memory");                     \
    for (int t = 0; t < NCHUNK; t++) {                                         \
        const int buf = t & 1;                                                 \
        asm volatile("cp.async.wait_group 1;\n" ::: "memory");                 \
        __syncthreads();                                                       \
        const uint32_t aBase = s2u(Abuf[buf]) + 4 * aOff;                      \
        const uint32_t wBase = s2u(Wbuf[buf]) + 4 * wOff;                      \
        _Pragma("unroll")                                                      \
        for (int s = 0; s < 2; s++) {                                          \
            uint32_t ah[2][4], am[2][4];                                       \
            _Pragma("unroll")                                                  \
            for (int mi = 0; mi < 2; mi++) {                                   \
                ldm_x4(ah[mi][0], ah[mi][1], ah[mi][2], ah[mi][3],             \
                       aBase + 4 * (16 * mi * GSTR + 8 * s));                  \
                ldm_x4(am[mi][0], am[mi][1], am[mi][2], am[mi][3],             \
                       aBase + 4 * (16 * mi * GSTR + 16 + 8 * s));             \
            }                                                                  \
            _Pragma("unroll")                                                  \
            for (int njp = 0; njp < 4; njp++) {                                \
                uint32_t bh0, bh1, bh2, bh3, bm0, bm1, bm2, bm3;               \
                ldm_x4(bh0, bh1, bh2, bh3,                                     \
                       wBase + 4 * (16 * njp * GSTR + 8 * s));                 \
                ldm_x4(bm0, bm1, bm2, bm3,                                     \
                       wBase + 4 * (16 * njp * GSTR + 16 + 8 * s));            \
                mma3b(acc[0][2*njp    ], ah[0], am[0], bh0, bh1, bm0, bm1);    \
                mma3b(acc[1][2*njp    ], ah[1], am[1], bh0, bh1, bm0, bm1);    \
                mma3b(acc[0][2*njp + 1], ah[0], am[0], bh2, bh3, bm2, bm3);    \
                mma3b(acc[1][2*njp + 1], ah[1], am[1], bh2, bh3, bm2, bm3);    \
            }                                                                  \
        }                                                                      \
        __syncthreads();                                                       \
        if (t + 2 < NCHUNK) load_stage(t + 2, buf);                            \
        asm volatile("cp.async.commit_group;\n" ::: "memory");                 \
    }

// ---------------------------------------------------------------------------
// Fused QKV GEMM: W = wqkv2 (1536 rows), bias3 concat, split-packed output
// routed to q2/k2/v2 by column segment. Grid (12, 128).
// ---------------------------------------------------------------------------
__global__ __launch_bounds__(256, 2) void gemm_qkv_kernel(
    const uint32_t* __restrict__ A2, const uint32_t* __restrict__ W2,
    const float* __restrict__ bias3,
    uint32_t* __restrict__ q2, uint32_t* __restrict__ k2,
    uint32_t* __restrict__ v2)
{
    GEMM_PROLOG(A2, W2)

    const int seg = nb >> 9;                       // 0=q,1=k,2=v (const/block)
    uint32_t* C = (seg == 0) ? q2 : (seg == 1) ? k2 : v2;

    #pragma unroll
    for (int mi = 0; mi < 2; mi++) {
        int r0 = mb + wm + mi * 16 + g;
        #pragma unroll
        for (int nj = 0; nj < 8; nj++) {
            int c0g = nb + wn + nj * 8 + 2 * tg;   // global col in [0,1536)
            int c0  = c0g & 511;                   // col within segment
            float bia0 = bias3[c0g], bia1 = bias3[c0g + 1];
            float v00 = acc[mi][nj][0] + bia0;
            float v01 = acc[mi][nj][1] + bia1;
            float v10 = acc[mi][nj][2] + bia0;
            float v11 = acc[mi][nj][3] + bia1;
            uint32_t hi, mid;
            split2(v00, v01, hi, mid);
            C[(size_t)r0 * ROWU + (c0 >> 1)]       = hi;
            C[(size_t)r0 * ROWU + 256 + (c0 >> 1)] = mid;
            split2(v10, v11, hi, mid);
            C[(size_t)(r0 + 8) * ROWU + (c0 >> 1)]       = hi;
            C[(size_t)(r0 + 8) * ROWU + 256 + (c0 >> 1)] = mid;
        }
    }
}

// ---------------------------------------------------------------------------
// O projection GEMM: plain float output. Grid (4, 128).
// ---------------------------------------------------------------------------
__global__ __launch_bounds__(256, 2) void gemm_o_kernel(
    const uint32_t* __restrict__ A2, const uint32_t* __restrict__ W2,
    const float* __restrict__ bias, float* __restrict__ C)
{
    GEMM_PROLOG(A2, W2)

    #pragma unroll
    for (int mi = 0; mi < 2; mi++) {
        int r0 = mb + wm + mi * 16 + g;
        #pragma unroll
        for (int nj = 0; nj < 8; nj++) {
            int c0 = nb + wn + nj * 8 + 2 * tg;
            float bia0 = bias[c0], bia1 = bias[c0 + 1];
            *(float2*)&C[(size_t)r0 * D_ + c0] =
                make_float2(acc[mi][nj][0] + bia0, acc[mi][nj][1] + bia1);
            *(float2*)&C[(size_t)(r0 + 8) * D_ + c0] =
                make_float2(acc[mi][nj][2] + bia0, acc[mi][nj][3] + bia1);
        }
    }
}

// ---------------------------------------------------------------------------
// bf16-split attention — R14 shape (256 thr / 8 warps, 128 q/CTA, 3-stage
// cp.async, wait_group 2, two syncs, refill after compute), with V loaded
// ROW-MAJOR like K and PV B-fragments fetched via ldmatrix.trans.
// No V transpose kernel, no v2t buffer.
// ---------------------------------------------------------------------------
#define KSTR 68                 // smem row: [hi 32 u32][mid 32][pad 4]
#define KTILE (32*KSTR)         // one K or V tile (32 rows)
#define NSTAGE 3
#define NTILES (N_/32)
#define ATHR 256

__global__ __launch_bounds__(ATHR, 2) void attn_bf16_kernel(
    const uint32_t* __restrict__ q2, const uint32_t* __restrict__ k2,
    const uint32_t* __restrict__ v2, uint32_t* __restrict__ ctx2)
{
    extern __shared__ uint32_t sma[];
    uint32_t* Kb[NSTAGE];
    uint32_t* Vb[NSTAGE];
    #pragma unroll
    for (int i = 0; i < NSTAGE; i++) {
        Kb[i] = sma + i * KTILE;
        Vb[i] = sma + NSTAGE * KTILE + i * KTILE;
    }

    const int tid  = threadIdx.x;
    const int lane = tid & 31, warp = tid >> 5;
    const int g    = lane >> 2, tg = lane & 3;
    const int wm   = warp * 16;                 // 0..112 (8 warps)

    const int hidx = blockIdx.y;
    const int h    = hidx & (H_ - 1);
    const int tb   = hidx >> 3;
    const int tokb = tb * N_;
    const int q0   = blockIdx.x * 128;          // 128 queries per CTA

    // K fragments: non-trans (K rows are keys = n, cols are ch = k)
    const uint32_t kOff = (uint32_t)((lane & 7) * KSTR +
                                     ((lane >> 3) & 1) * 4 +
                                     (lane >> 4) * 8 * KSTR);
    // V fragments: TRANS (V rows are keys = k, cols are ch = n)
    const uint32_t vOff = (uint32_t)((lane & 15) * KSTR + (lane >> 4) * 4);

    auto load_rows = [&](const uint32_t* gsrc, uint32_t* sdst, int k0) {
        #pragma unroll
        for (int l = tid; l < 512; l += ATHR) {   // 32 rows x 64 u32
            int key = l >> 4, part = l & 15;
            size_t rowb = (size_t)(tokb + k0 + key) * ROWU + h * 32;
            size_t src; uint32_t dst;
            if (part < 8) {
                src = rowb + 4 * part;
                dst = s2u(&sdst[key * KSTR + 4 * part]);
            } else {
                src = rowb + 256 + 4 * (part - 8);
                dst = s2u(&sdst[key * KSTR + 32 + 4 * (part - 8)]);
            }
            cpa16(dst, &gsrc[src]);
        }
    };
    auto load_tile = [&](int t, int buf) {
        load_rows(k2, Kb[buf], 32 * t);
        load_rows(v2, Vb[buf], 32 * t);
    };

    #pragma unroll
    for (int p = 0; p < NSTAGE; p++) {
        load_tile(p, p);
        asm volatile("cp.async.commit_group;\n" ::: "memory");
    }

    // ---- Q fragments -> registers ----
    uint32_t qh[4][4], qm[4][4];
    {
        size_t rA = (size_t)(tokb + q0 + wm + g) * ROWU + h * 32;
        size_t rB = rA + (size_t)8 * ROWU;
        #pragma unroll
        for (int s = 0; s < 4; s++) {
            qh[s][0] = q2[rA + 8*s + tg];        qh[s][1] = q2[rB + 8*s + tg];
            qh[s][2] = q2[rA + 8*s + tg + 4];    qh[s][3] = q2[rB + 8*s + tg + 4];
            qm[s][0] = q2[rA + 256 + 8*s + tg];      qm[s][1] = q2[rB + 256 + 8*s + tg];
            qm[s][2] = q2[rA + 256 + 8*s + tg + 4];  qm[s][3] = q2[rB + 256 + 8*s + tg + 4];
        }
    }

    float accPV[8][4];
    #pragma unroll
    for (int j = 0; j < 8; j++)
        #pragma unroll
        for (int l = 0; l < 4; l++) accPV[j][l] = 0.f;
    float dA = 0.f, dB = 0.f;

    int buf = 0;
    for (int t = 0; t < NTILES; t++) {
        asm volatile("cp.async.wait_group 2;\n" ::: "memory");
        __syncthreads();

        const uint32_t kBase = s2u(Kb[buf]) + 4 * kOff;
        const uint32_t vBase = s2u(Vb[buf]) + 4 * vOff;

        // ---- S = Q K^T : 16 rows x 32 keys ----
        float accS[4][4];
        #pragma unroll
        for (int j = 0; j < 4; j++)
            #pragma unroll
            for (int l = 0; l < 4; l++) accS[j][l] = 0.f;

        #pragma unroll
        for (int s = 0; s < 4; s++) {
            #pragma unroll
            for (int njp = 0; njp < 2; njp++) {
                uint32_t bh0, bh1, bh2, bh3, bm0, bm1, bm2, bm3;
                ldm_x4(bh0, bh1, bh2, bh3,
                       kBase + 4 * (16 * njp * KSTR + 8 * s));
                ldm_x4(bm0, bm1, bm2, bm3,
                       kBase + 4 * (16 * njp * KSTR + 32 + 8 * s));
                mma3b(accS[2*njp    ], qh[s], qm[s], bh0, bh1, bm0, bm1);
                mma3b(accS[2*njp + 1], qh[s], qm[s], bh2, bh3, bm2, bm3);
            }
        }

        // ---- P = relu(S/8) in-lane -> A frags; denom; PV ----
        #pragma unroll
        for (int kb = 0; kb < 2; kb++) {
            float p0 = fmaxf(accS[2*kb    ][0] * 0.125f, 0.f);
            float p1 = fmaxf(accS[2*kb    ][1] * 0.125f, 0.f);
            float p2 = fmaxf(accS[2*kb    ][2] * 0.125f, 0.f);
            float p3 = fmaxf(accS[2*kb    ][3] * 0.125f, 0.f);
            float p4 = fmaxf(accS[2*kb + 1][0] * 0.125f, 0.f);
            float p5 = fmaxf(accS[2*kb + 1][1] * 0.125f, 0.f);
            float p6 = fmaxf(accS[2*kb + 1][2] * 0.125f, 0.f);
            float p7 = fmaxf(accS[2*kb + 1][3] * 0.125f, 0.f);
            dA += p0 + p1 + p4 + p5;
            dB += p2 + p3 + p6 + p7;

            uint32_t ah[4], am[4];
            split2(p0, p1, ah[0], am[0]);
            split2(p2, p3, ah[1], am[1]);
            split2(p4, p5, ah[2], am[2]);
            split2(p6, p7, ah[3], am[3]);

            // V via ldmatrix.trans: rows = keys (16 per kb), cols = channels.
            #pragma unroll
            for (int njp = 0; njp < 4; njp++) {
                uint32_t bh0, bh1, bh2, bh3, bm0, bm1, bm2, bm3;
                ldm_x4t(bh0, bh1, bh2, bh3,
                        vBase + 4 * (16 * kb * KSTR + 8 * njp));
                ldm_x4t(bm0, bm1, bm2, bm3,
                        vBase + 4 * (16 * kb * KSTR + 32 + 8 * njp));
                mma3b(accPV[2*njp    ], ah, am, bh0, bh1, bm0, bm1);
                mma3b(accPV[2*njp + 1], ah, am, bh2, bh3, bm2, bm3);
            }
        }
        __syncthreads();   // all warps done with buf before refill

        if (t + NSTAGE < NTILES) load_tile(t + NSTAGE, buf);
        asm volatile("cp.async.commit_group;\n" ::: "memory");

        buf = (buf == NSTAGE - 1) ? 0 : buf + 1;
    }

    // ---- denominator reduce over tg lanes ----
    dA += __shfl_xor_sync(0xffffffffu, dA, 1);
    dA += __shfl_xor_sync(0xffffffffu, dA, 2);
    dB += __shfl_xor_sync(0xffffffffu, dB, 1);
    dB += __shfl_xor_sync(0xffffffffu, dB, 2);
    const float invA = 1.f / (dA + 1e-6f);
    const float invB = 1.f / (dB + 1e-6f);

    // ---- write ctx packed (planes) for O projection ----
    size_t rA = (size_t)(tokb + q0 + wm + g) * ROWU + h * 32;
    size_t rB = rA + (size_t)8 * ROWU;
    #pragma unroll
    for (int nj = 0; nj < 8; nj++) {
        uint32_t hi, mid;
        split2(accPV[nj][0] * invA, accPV[nj][1] * invA, hi, mid);
        ctx2[rA + 4*nj + tg]       = hi;
        ctx2[rA + 256 + 4*nj + tg] = mid;
        split2(accPV[nj][2] * invB, accPV[nj][3] * invB, hi, mid);
        ctx2[rB + 4*nj + tg]       = hi;
        ctx2[rB + 256 + 4*nj + tg] = mid;
    }
}

// ---------------------------------------------------------------------------
// Launcher. Input order: x, wq, bq, wk, bk, wv, bv, wo, bo
// ---------------------------------------------------------------------------
extern "C" void kernel_launch(void* const* d_in, const int* in_sizes, int n_in,
                              void* d_out, int out_size)
{
    const float* x  = (const float*)d_in[0];
    const float* wq = (const float*)d_in[1];
    const float* bq = (const float*)d_in[2];
    const float* wk = (const float*)d_in[3];
    const float* bk = (const float*)d_in[4];
    const float* wv = (const float*)d_in[5];
    const float* bv = (const float*)d_in[6];
    const float* wo = (const float*)d_in[7];
    const float* bo = (const float*)d_in[8];
    float* out = (float*)d_out;

    uint32_t *x2, *q2, *k2, *v2, *wqkv2, *wo2;
    float* bias3;
    cudaGetSymbolAddress((void**)&x2,    gU_x2);
    cudaGetSymbolAddress((void**)&q2,    gU_q2);
    cudaGetSymbolAddress((void**)&k2,    gU_k2);
    cudaGetSymbolAddress((void**)&v2,    gU_v2);
    cudaGetSymbolAddress((void**)&wqkv2, gU_wqkv2);
    cudaGetSymbolAddress((void**)&wo2,   gU_wo2);
    cudaGetSymbolAddress((void**)&bias3, g_bias3);

    const int gemm_smem = 4 * GSTG * (int)sizeof(uint32_t);          // 73,728 B
    const int attn_smem = NSTAGE * 2 * KTILE * (int)sizeof(uint32_t); // 52,224 B
    cudaFuncSetAttribute(gemm_qkv_kernel,
        cudaFuncAttributeMaxDynamicSharedMemorySize, gemm_smem);
    cudaFuncSetAttribute(gemm_o_kernel,
        cudaFuncAttributeMaxDynamicSharedMemorySize, gemm_smem);
    cudaFuncSetAttribute(attn_bf16_kernel,
        cudaFuncAttributeMaxDynamicSharedMemorySize, attn_smem);

    // ---- fused pack (x + 4 weights + bias concat) ----
    pack_all_kernel<<<PACK_TOTAL / 256, 256>>>(
        x, wq, wk, wv, wo, bq, bk, bv, x2, wqkv2, wo2, bias3);

    // ---- fused QKV projection ----
    dim3 gQKV(3 * D_ / 128, M_ / 128);     // 12 x 128
    gemm_qkv_kernel<<<gQKV, 256, gemm_smem>>>(x2, wqkv2, bias3, q2, k2, v2);

    // ---- attention (consumes v2 directly; no transpose kernel) ----
    dim3 gAttn(N_ / 128, T_ * B_ * H_);    // 8 x 128
    attn_bf16_kernel<<<gAttn, ATHR, attn_smem>>>(q2, k2, v2, x2);  // ctx -> x2

    dim3 gO(D_ / 128, M_ / 128);           // 4 x 128
    gemm_o_kernel<<<gO, 256, gemm_smem>>>(x2, wo2, bo, out);
}